// round 10
// baseline (speedup 1.0000x reference)
#include <cuda_runtime.h>
#include <cuda_fp16.h>
#include <cstdint>
#include <cstddef>

// Problem constants
#define B_    4
#define C_    256
#define NH_   8
#define Mtot  262144          // B * H * W tokens
#define NWIN  4096            // B * 32 * 32 windows

// Scratch (allocation-free rule: __device__ globals)
__device__ __half g_x16 [(size_t)Mtot * 256];   // x in fp16
__device__ __half g_wq16[768 * 256];            // qkv_w in fp16
__device__ __half g_wp16[256 * 256];            // proj_w in fp16
__device__ __half g_qkv [(size_t)Mtot * 768];   // qkv, natural token order, fp16
__device__ __half g_att [(size_t)Mtot * 256];   // attn out, natural order, fp16

// ---------------------------------------------------------------------------
// helpers
// ---------------------------------------------------------------------------
__device__ __forceinline__ float tf32r(float x) {
    uint32_t u;
    asm("cvt.rna.tf32.f32 %0, %1;" : "=r"(u) : "f"(x));
    return __uint_as_float(u);
}

__device__ __forceinline__ void mma16(float c[4], const uint32_t a[4], const uint32_t b[2]) {
    asm volatile(
        "mma.sync.aligned.m16n8k16.row.col.f32.f16.f16.f32 "
        "{%0,%1,%2,%3}, {%4,%5,%6,%7}, {%8,%9}, {%0,%1,%2,%3};\n"
        : "+f"(c[0]), "+f"(c[1]), "+f"(c[2]), "+f"(c[3])
        : "r"(a[0]), "r"(a[1]), "r"(a[2]), "r"(a[3]), "r"(b[0]), "r"(b[1]));
}

// tf32 mma for attention (known-good numerics)
__device__ __forceinline__ void mma8(float c[4], const uint32_t a[4], const uint32_t b[2]) {
    asm volatile(
        "mma.sync.aligned.m16n8k8.row.col.f32.tf32.tf32.f32 "
        "{%0,%1,%2,%3}, {%4,%5,%6,%7}, {%8,%9}, {%0,%1,%2,%3};\n"
        : "+f"(c[0]), "+f"(c[1]), "+f"(c[2]), "+f"(c[3])
        : "r"(a[0]), "r"(a[1]), "r"(a[2]), "r"(a[3]), "r"(b[0]), "r"(b[1]));
}

__device__ __forceinline__ void cpa16(void* dst, const void* src) {
    uint32_t d = (uint32_t)__cvta_generic_to_shared(dst);
    asm volatile("cp.async.cg.shared.global [%0], [%1], 16;\n" :: "r"(d), "l"(src));
}
__device__ __forceinline__ void cpa_commit() {
    asm volatile("cp.async.commit_group;\n" ::: "memory");
}
template <int N>
__device__ __forceinline__ void cpa_wait() {
    asm volatile("cp.async.wait_group %0;\n" :: "n"(N) : "memory");
}

// ---------------------------------------------------------------------------
// fp16 GEMM, 2-stage cp.async pipeline:
// C[M,N] = A[M,K] @ B[N,K]^T (+ bias[N]),  A,B fp16, accum fp32, OutT output
// BM=128, BN=128, BK=32, 128 threads, 4 warps (2x2), warp tile 64x64
// smem rows: 32 halves data + 8 pad = 40 halves (80B stride; conflict-free
// fragment LDS: word index = row*20 + tig pattern covers all 32 banks)
// ---------------------------------------------------------------------------
#define BM 128
#define BN 128
#define BK 32
#define ROWH 40                 // halves per smem row (80 B)
#define TILEB (BM * ROWH * 2)   // 10240 B per stage
// layout in sraw: A stage0 | A stage1 | B stage0 | B stage1
#define AOFF(s) ((s) * TILEB)
#define BOFF(s) (2 * TILEB + (s) * TILEB)

template <typename OutT>
__global__ __launch_bounds__(128) void gemm_f16(
    const __half* __restrict__ A, const __half* __restrict__ Bw,
    const float* __restrict__ bias, OutT* __restrict__ C,
    int N, int K)
{
    __shared__ __align__(16) unsigned char sraw[4 * TILEB];   // 40 KB

    const int tid  = threadIdx.x;
    const int mT   = blockIdx.y * BM;
    const int nT   = blockIdx.x * BN;
    const int lane = tid & 31;
    const int warp = tid >> 5;
    const int gid  = lane >> 2;
    const int tig  = lane & 3;
    const int wm   = (warp & 1) * 64;
    const int wn   = (warp >> 1) * 64;

    float c[4][8][4];
#pragma unroll
    for (int i = 0; i < 4; i++)
#pragma unroll
        for (int j = 0; j < 8; j++)
#pragma unroll
            for (int r = 0; r < 4; r++) c[i][j][r] = 0.f;

    // copy map: per tile 128 rows x 32 halves = 512 x 16B; 4 per thread
    const int rc = tid >> 2;             // base row 0..31
    const int cc = (tid & 3) << 3;       // half-offset 0,8,16,24

    auto issue = [&](int s, int k0) {
        const __half* ab = A  + (size_t)(mT + rc) * K + k0 + cc;
        const __half* bb = Bw + (size_t)(nT + rc) * K + k0 + cc;
#pragma unroll
        for (int it = 0; it < 4; it++) {
            int row = rc + it * 32;
            cpa16(sraw + AOFF(s) + row * 80 + (cc << 1), ab + (size_t)it * 32 * K);
            cpa16(sraw + BOFF(s) + row * 80 + (cc << 1), bb + (size_t)it * 32 * K);
        }
        cpa_commit();
    };

    issue(0, 0);
    const int NT = K >> 5;

    for (int kt = 0; kt < NT; kt++) {
        if (kt + 1 < NT) {
            issue((kt + 1) & 1, (kt + 1) * BK);
            cpa_wait<1>();
        } else {
            cpa_wait<0>();
        }
        __syncthreads();

        const int s = kt & 1;
        const unsigned char* ap = sraw + AOFF(s);
        const unsigned char* bp = sraw + BOFF(s);
#pragma unroll
        for (int kk = 0; kk < BK; kk += 16) {
            uint32_t af[4][4], bf[8][2];
#pragma unroll
            for (int mf = 0; mf < 4; mf++) {
                int m = wm + mf * 16 + gid;
                af[mf][0] = *(const uint32_t*)(ap + m * 80 + (kk + 2 * tig) * 2);
                af[mf][1] = *(const uint32_t*)(ap + (m + 8) * 80 + (kk + 2 * tig) * 2);
                af[mf][2] = *(const uint32_t*)(ap + m * 80 + (kk + 2 * tig + 8) * 2);
                af[mf][3] = *(const uint32_t*)(ap + (m + 8) * 80 + (kk + 2 * tig + 8) * 2);
            }
#pragma unroll
            for (int nf = 0; nf < 8; nf++) {
                int n = wn + nf * 8 + gid;
                bf[nf][0] = *(const uint32_t*)(bp + n * 80 + (kk + 2 * tig) * 2);
                bf[nf][1] = *(const uint32_t*)(bp + n * 80 + (kk + 2 * tig + 8) * 2);
            }
#pragma unroll
            for (int mf = 0; mf < 4; mf++)
#pragma unroll
                for (int nf = 0; nf < 8; nf++)
                    mma16(c[mf][nf], af[mf], bf[nf]);
        }
        __syncthreads();
    }

    // epilogue: per-warp smem staging -> fully coalesced gmem rows
    OutT* stg = (OutT*)sraw + warp * (64 * 36);
#pragma unroll 1
    for (int cb = 0; cb < 2; cb++) {
#pragma unroll
        for (int mf = 0; mf < 4; mf++) {
#pragma unroll
            for (int nf2 = 0; nf2 < 4; nf2++) {
                int nf = cb * 4 + nf2;
                int lr = mf * 16 + gid;
                int lc = nf2 * 8 + 2 * tig;
                float b0 = 0.f, b1 = 0.f;
                if (bias) {
                    int gcol = nT + wn + cb * 32 + lc;
                    b0 = bias[gcol]; b1 = bias[gcol + 1];
                }
                stg[lr * 36 + lc]           = (OutT)(c[mf][nf][0] + b0);
                stg[lr * 36 + lc + 1]       = (OutT)(c[mf][nf][1] + b1);
                stg[(lr + 8) * 36 + lc]     = (OutT)(c[mf][nf][2] + b0);
                stg[(lr + 8) * 36 + lc + 1] = (OutT)(c[mf][nf][3] + b1);
            }
        }
        __syncwarp();
        const int gc0 = nT + wn + cb * 32;
        if (sizeof(OutT) == 4) {
            // 32 floats = 128B per row, one lane per column
#pragma unroll 4
            for (int r = 0; r < 64; r++)
                C[(size_t)(mT + wm + r) * N + gc0 + lane] = stg[r * 36 + lane];
        } else {
            // 32 halves = 64B per row; 2 rows per pass
#pragma unroll 4
            for (int r2 = 0; r2 < 32; r2++) {
                int row  = r2 * 2 + (lane >> 4);
                int colh = (lane & 15) * 2;
                *(uint32_t*)&C[(size_t)(mT + wm + row) * N + gc0 + colh] =
                    *(const uint32_t*)&stg[row * 36 + colh];
            }
        }
        __syncwarp();
    }
}

// ---------------------------------------------------------------------------
// fp32 -> fp16 conversion pre-pass
// ---------------------------------------------------------------------------
__global__ void f2h_k(const float4* __restrict__ s, __half2* __restrict__ d, int n4)
{
    int i = blockIdx.x * blockDim.x + threadIdx.x;
    if (i < n4) {
        float4 v = s[i];
        d[2 * i]     = __floats2half2_rn(v.x, v.y);
        d[2 * i + 1] = __floats2half2_rn(v.z, v.w);
    }
}

// ---------------------------------------------------------------------------
// Window attention: one CTA per (window, head), 128 threads (4 warps).
// fp16 I/O, tf32 mma compute (identical numerics path to the passing kernel).
// ---------------------------------------------------------------------------
__global__ __launch_bounds__(128) void win_attn(
    const __half* __restrict__ qkv, const float* __restrict__ bias,
    __half* __restrict__ outp)
{
    __shared__ float Qs[64][36];
    __shared__ float Ks[64][36];
    __shared__ float Vs[64][36];
    __shared__ float Ss[64][68];

    const int w   = blockIdx.x;
    const int h   = blockIdx.y;
    const int b   = w >> 10;
    const int rem = w & 1023;
    const int wh  = rem >> 5;
    const int ww  = rem & 31;
    const int base_l = (b << 16) + (wh << 3) * 256 + (ww << 3);

    const int tid = threadIdx.x;
    const float scale = 0.17677669529663687f;   // 1/sqrt(32)

    // load q,k,v tiles (64 x 32 halves each): 2 iters x 16B per tensor
#pragma unroll
    for (int it = 0; it < 2; it++) {
        int v   = tid + it * 128;               // 0..255
        int row = v >> 2;                       // token 0..63
        int c8  = (v & 3) << 3;                 // 0,8,16,24
        int l   = base_l + ((row >> 3) << 8) + (row & 7);
        const __half* rp = qkv + (size_t)l * 768 + (h << 5) + c8;
        uint4 qd = *(const uint4*)(rp);
        uint4 kd = *(const uint4*)(rp + 256);
        uint4 vd = *(const uint4*)(rp + 512);
        const __half2* qh = (const __half2*)&qd;
        const __half2* kh = (const __half2*)&kd;
        const __half2* vh = (const __half2*)&vd;
#pragma unroll
        for (int j = 0; j < 4; j++) {
            float2 qf = __half22float2(qh[j]);
            float2 kf = __half22float2(kh[j]);
            float2 vf = __half22float2(vh[j]);
            Qs[row][c8 + 2 * j]     = tf32r(qf.x * scale);
            Qs[row][c8 + 2 * j + 1] = tf32r(qf.y * scale);
            Ks[row][c8 + 2 * j]     = kf.x;   // fp16 values are tf32-exact
            Ks[row][c8 + 2 * j + 1] = kf.y;
            Vs[row][c8 + 2 * j]     = vf.x;
            Vs[row][c8 + 2 * j + 1] = vf.y;
        }
    }
    __syncthreads();

    const int lane = tid & 31, warp = tid >> 5;
    const int gid = lane >> 2, tig = lane & 3;
    const int mB = warp << 4;
    const int r0 = mB + gid, r1 = r0 + 8;

    // S = q*scale @ k^T  (64x64, each warp 16 rows)
    float c[8][4];
#pragma unroll
    for (int nf = 0; nf < 8; nf++)
#pragma unroll
        for (int r = 0; r < 4; r++) c[nf][r] = 0.f;

#pragma unroll
    for (int kc = 0; kc < 4; kc++) {
        uint32_t a[4];
        a[0] = __float_as_uint(Qs[r0][kc * 8 + tig]);
        a[1] = __float_as_uint(Qs[r1][kc * 8 + tig]);
        a[2] = __float_as_uint(Qs[r0][kc * 8 + tig + 4]);
        a[3] = __float_as_uint(Qs[r1][kc * 8 + tig + 4]);
#pragma unroll
        for (int nf = 0; nf < 8; nf++) {
            uint32_t bf[2];
            bf[0] = __float_as_uint(Ks[nf * 8 + gid][kc * 8 + tig]);
            bf[1] = __float_as_uint(Ks[nf * 8 + gid][kc * 8 + tig + 4]);
            mma8(c[nf], a, bf);
        }
    }

    // + bias, then row softmax
    const float* bp = bias + (h << 12);
    float mx0 = -1e30f, mx1 = -1e30f;
#pragma unroll
    for (int nf = 0; nf < 8; nf++) {
        int col = nf * 8 + 2 * tig;
        float2 b0 = *(const float2*)(bp + r0 * 64 + col);
        float2 b1 = *(const float2*)(bp + r1 * 64 + col);
        c[nf][0] += b0.x; c[nf][1] += b0.y;
        c[nf][2] += b1.x; c[nf][3] += b1.y;
        mx0 = fmaxf(mx0, fmaxf(c[nf][0], c[nf][1]));
        mx1 = fmaxf(mx1, fmaxf(c[nf][2], c[nf][3]));
    }
    mx0 = fmaxf(mx0, __shfl_xor_sync(0xffffffffu, mx0, 1));
    mx0 = fmaxf(mx0, __shfl_xor_sync(0xffffffffu, mx0, 2));
    mx1 = fmaxf(mx1, __shfl_xor_sync(0xffffffffu, mx1, 1));
    mx1 = fmaxf(mx1, __shfl_xor_sync(0xffffffffu, mx1, 2));

    float s0 = 0.f, s1 = 0.f;
#pragma unroll
    for (int nf = 0; nf < 8; nf++) {
        c[nf][0] = __expf(c[nf][0] - mx0); s0 += c[nf][0];
        c[nf][1] = __expf(c[nf][1] - mx0); s0 += c[nf][1];
        c[nf][2] = __expf(c[nf][2] - mx1); s1 += c[nf][2];
        c[nf][3] = __expf(c[nf][3] - mx1); s1 += c[nf][3];
    }
    s0 += __shfl_xor_sync(0xffffffffu, s0, 1);
    s0 += __shfl_xor_sync(0xffffffffu, s0, 2);
    s1 += __shfl_xor_sync(0xffffffffu, s1, 1);
    s1 += __shfl_xor_sync(0xffffffffu, s1, 2);
    float i0 = 1.f / s0, i1 = 1.f / s1;

#pragma unroll
    for (int nf = 0; nf < 8; nf++) {
        int col = nf * 8 + 2 * tig;
        Ss[r0][col]     = tf32r(c[nf][0] * i0);
        Ss[r0][col + 1] = tf32r(c[nf][1] * i0);
        Ss[r1][col]     = tf32r(c[nf][2] * i1);
        Ss[r1][col + 1] = tf32r(c[nf][3] * i1);
    }
    __syncthreads();

    // O = P @ V  (64x32)
    float o[4][4];
#pragma unroll
    for (int nf = 0; nf < 4; nf++)
#pragma unroll
        for (int r = 0; r < 4; r++) o[nf][r] = 0.f;

#pragma unroll
    for (int kc = 0; kc < 8; kc++) {
        uint32_t a[4];
        a[0] = __float_as_uint(Ss[r0][kc * 8 + tig]);
        a[1] = __float_as_uint(Ss[r1][kc * 8 + tig]);
        a[2] = __float_as_uint(Ss[r0][kc * 8 + tig + 4]);
        a[3] = __float_as_uint(Ss[r1][kc * 8 + tig + 4]);
#pragma unroll
        for (int nf = 0; nf < 4; nf++) {
            uint32_t bf[2];
            bf[0] = __float_as_uint(Vs[kc * 8 + tig    ][nf * 8 + gid]);
            bf[1] = __float_as_uint(Vs[kc * 8 + tig + 4][nf * 8 + gid]);
            mma8(o[nf], a, bf);
        }
    }

    // scatter fp16 to natural token order (GEMM3's A operand)
    const int l0 = base_l + ((r0 >> 3) << 8) + (r0 & 7);
    const int l1 = base_l + ((r1 >> 3) << 8) + (r1 & 7);
#pragma unroll
    for (int nf = 0; nf < 4; nf++) {
        int col = (h << 5) + nf * 8 + 2 * tig;
        *(__half2*)(outp + (size_t)l0 * 256 + col) = __floats2half2_rn(o[nf][0], o[nf][1]);
        *(__half2*)(outp + (size_t)l1 * 256 + col) = __floats2half2_rn(o[nf][2], o[nf][3]);
    }
}

// ---------------------------------------------------------------------------
// launch
// ---------------------------------------------------------------------------
extern "C" void kernel_launch(void* const* d_in, const int* in_sizes, int n_in,
                              void* d_out, int out_size)
{
    const float* x      = (const float*)d_in[0];
    const float* qkv_w  = (const float*)d_in[1];
    const float* proj_w = (const float*)d_in[2];
    const float* proj_b = (const float*)d_in[3];
    const float* bias   = (const float*)d_in[4];
    float* out = (float*)d_out;

    __half *x16, *wq16, *wp16, *qkv16, *att16;
    cudaGetSymbolAddress((void**)&x16,   g_x16);
    cudaGetSymbolAddress((void**)&wq16,  g_wq16);
    cudaGetSymbolAddress((void**)&wp16,  g_wp16);
    cudaGetSymbolAddress((void**)&qkv16, g_qkv);
    cudaGetSymbolAddress((void**)&att16, g_att);

    // fp32 -> fp16 pre-pass for all GEMM operands
    f2h_k<<<(Mtot * 256 / 4 + 255) / 256, 256>>>((const float4*)x,
                                                 (__half2*)x16, Mtot * 256 / 4);
    f2h_k<<<(768 * 256 / 4 + 255) / 256, 256>>>((const float4*)qkv_w,
                                                (__half2*)wq16, 768 * 256 / 4);
    f2h_k<<<(256 * 256 / 4 + 255) / 256, 256>>>((const float4*)proj_w,
                                                (__half2*)wp16, 256 * 256 / 4);

    // QKV projection: [262144,256] @ [768,256]^T -> fp16 [262144,768]
    gemm_f16<__half><<<dim3(768 / BN, Mtot / BM), 128>>>(x16, wq16, nullptr,
                                                         qkv16, 768, 256);
    // window attention (fp16 I/O, tf32 compute)
    win_attn<<<dim3(NWIN, NH_), 128>>>(qkv16, bias, att16);
    // output projection: [262144,256] @ [256,256]^T + b -> fp32 d_out
    gemm_f16<float><<<dim3(256 / BN, Mtot / BM), 128>>>(att16, wp16, proj_b,
                                                        out, 256, 256);
}

// round 11
// speedup vs baseline: 2.9922x; 2.9922x over previous
#include <cuda_runtime.h>
#include <cuda_fp16.h>
#include <cstdint>
#include <cstddef>

// Problem constants
#define B_    4
#define C_    256
#define NH_   8
#define Mtot  262144          // B * H * W tokens
#define NWIN  4096            // B * 32 * 32 windows

// Scratch (allocation-free rule: __device__ globals)
__device__ __half g_x16 [(size_t)Mtot * 256];   // x in fp16
__device__ __half g_wq16[768 * 256];            // qkv_w in fp16
__device__ __half g_wp16[256 * 256];            // proj_w in fp16
__device__ __half g_qkv [(size_t)Mtot * 768];   // qkv, natural token order, fp16
__device__ __half g_att [(size_t)Mtot * 256];   // attn out, natural order, fp16

// ---------------------------------------------------------------------------
// helpers
// ---------------------------------------------------------------------------
__device__ __forceinline__ float tf32r(float x) {
    uint32_t u;
    asm("cvt.rna.tf32.f32 %0, %1;" : "=r"(u) : "f"(x));
    return __uint_as_float(u);
}

__device__ __forceinline__ void mma16(float c[4], const uint32_t a[4], const uint32_t b[2]) {
    asm volatile(
        "mma.sync.aligned.m16n8k16.row.col.f32.f16.f16.f32 "
        "{%0,%1,%2,%3}, {%4,%5,%6,%7}, {%8,%9}, {%0,%1,%2,%3};\n"
        : "+f"(c[0]), "+f"(c[1]), "+f"(c[2]), "+f"(c[3])
        : "r"(a[0]), "r"(a[1]), "r"(a[2]), "r"(a[3]), "r"(b[0]), "r"(b[1]));
}

// tf32 mma for attention (known-good numerics)
__device__ __forceinline__ void mma8(float c[4], const uint32_t a[4], const uint32_t b[2]) {
    asm volatile(
        "mma.sync.aligned.m16n8k8.row.col.f32.tf32.tf32.f32 "
        "{%0,%1,%2,%3}, {%4,%5,%6,%7}, {%8,%9}, {%0,%1,%2,%3};\n"
        : "+f"(c[0]), "+f"(c[1]), "+f"(c[2]), "+f"(c[3])
        : "r"(a[0]), "r"(a[1]), "r"(a[2]), "r"(a[3]), "r"(b[0]), "r"(b[1]));
}

__device__ __forceinline__ void cpa16(void* dst, const void* src) {
    uint32_t d = (uint32_t)__cvta_generic_to_shared(dst);
    asm volatile("cp.async.cg.shared.global [%0], [%1], 16;\n" :: "r"(d), "l"(src));
}
__device__ __forceinline__ void cpa_commit() {
    asm volatile("cp.async.commit_group;\n" ::: "memory");
}
template <int N>
__device__ __forceinline__ void cpa_wait() {
    asm volatile("cp.async.wait_group %0;\n" :: "n"(N) : "memory");
}

__device__ __forceinline__ uint32_t ld_h2(const __half* p) {
    return *(const uint32_t*)p;
}

// ---------------------------------------------------------------------------
// fp16 GEMM, 2-stage cp.async pipeline (R7 register-lean skeleton):
// C[M,N] = A[M,K] @ B[N,K]^T (+ bias[N]),  A,B fp16, accum fp32, OutT out
// BM=128, BN=128, BKH=32 halves, 128 threads, 4 warps (2x2), warp tile 64x64
// smem [2][128][40] halves: 80B row stride, conflict-free fragment LDS
// ---------------------------------------------------------------------------
#define BM 128
#define BN 128
#define BKH 32
#define KPADH 40   // 40 halves = 80 B row stride

template <typename OutT>
__global__ __launch_bounds__(128, 3) void gemm_f16(
    const __half* __restrict__ A, const __half* __restrict__ Bw,
    const float* __restrict__ bias, OutT* __restrict__ C,
    int N, int K)
{
    __shared__ __align__(16) __half As[2][BM][KPADH];   // 20 KB
    __shared__ __align__(16) __half Bs[2][BN][KPADH];   // 20 KB

    const int tid  = threadIdx.x;
    const int mT   = blockIdx.y * BM;
    const int nT   = blockIdx.x * BN;
    const int lane = tid & 31;
    const int warp = tid >> 5;
    const int gid  = lane >> 2;
    const int tig  = lane & 3;
    const int wm   = (warp & 1) * 64;
    const int wn   = (warp >> 1) * 64;

    float c[4][8][4];
#pragma unroll
    for (int i = 0; i < 4; i++)
#pragma unroll
        for (int j = 0; j < 8; j++)
#pragma unroll
            for (int r = 0; r < 4; r++) c[i][j][r] = 0.f;

    // copy map: per tile 128 rows x 32 halves = 512 x 16B; 4 per thread each
    const int rc = tid >> 2;             // base row 0..31
    const int cc = (tid & 3) << 3;       // half offset 0,8,16,24

    auto issue = [&](int s, int k0) {
        const __half* ab = A  + (size_t)(mT + rc) * K + k0 + cc;
        const __half* bb = Bw + (size_t)(nT + rc) * K + k0 + cc;
#pragma unroll
        for (int it = 0; it < 4; it++) {
            int row = rc + it * 32;
            cpa16(&As[s][row][cc], ab + (size_t)it * 32 * K);
            cpa16(&Bs[s][row][cc], bb + (size_t)it * 32 * K);
        }
        cpa_commit();
    };

    issue(0, 0);
    const int NT = K >> 5;

    for (int kt = 0; kt < NT; kt++) {
        if (kt + 1 < NT) {
            issue((kt + 1) & 1, (kt + 1) * BKH);
            cpa_wait<1>();
        } else {
            cpa_wait<0>();
        }
        __syncthreads();

        const int s = kt & 1;
#pragma unroll
        for (int kk = 0; kk < BKH; kk += 16) {
            uint32_t af[4][4], bf[8][2];
#pragma unroll
            for (int mf = 0; mf < 4; mf++) {
                int m = wm + mf * 16 + gid;
                af[mf][0] = ld_h2(&As[s][m    ][kk + 2 * tig]);
                af[mf][1] = ld_h2(&As[s][m + 8][kk + 2 * tig]);
                af[mf][2] = ld_h2(&As[s][m    ][kk + 2 * tig + 8]);
                af[mf][3] = ld_h2(&As[s][m + 8][kk + 2 * tig + 8]);
            }
#pragma unroll
            for (int nf = 0; nf < 8; nf++) {
                int n = wn + nf * 8 + gid;
                bf[nf][0] = ld_h2(&Bs[s][n][kk + 2 * tig]);
                bf[nf][1] = ld_h2(&Bs[s][n][kk + 2 * tig + 8]);
            }
#pragma unroll
            for (int mf = 0; mf < 4; mf++)
#pragma unroll
                for (int nf = 0; nf < 8; nf++)
                    mma16(c[mf][nf], af[mf], bf[nf]);
        }
        __syncthreads();
    }

    // epilogue: per-fragment direct stores (register-lean, R7 style)
#pragma unroll
    for (int mf = 0; mf < 4; mf++) {
#pragma unroll
        for (int nf = 0; nf < 8; nf++) {
            int row = mT + wm + mf * 16 + gid;
            int col = nT + wn + nf * 8 + 2 * tig;
            float b0 = 0.f, b1 = 0.f;
            if (bias) { b0 = bias[col]; b1 = bias[col + 1]; }
            if (sizeof(OutT) == 2) {
                *(__half2*)((__half*)C + (size_t)row * N + col) =
                    __floats2half2_rn(c[mf][nf][0] + b0, c[mf][nf][1] + b1);
                *(__half2*)((__half*)C + (size_t)(row + 8) * N + col) =
                    __floats2half2_rn(c[mf][nf][2] + b0, c[mf][nf][3] + b1);
            } else {
                *(float2*)((float*)C + (size_t)row * N + col) =
                    make_float2(c[mf][nf][0] + b0, c[mf][nf][1] + b1);
                *(float2*)((float*)C + (size_t)(row + 8) * N + col) =
                    make_float2(c[mf][nf][2] + b0, c[mf][nf][3] + b1);
            }
        }
    }
}

// ---------------------------------------------------------------------------
// fp32 -> fp16 conversion pre-pass
// ---------------------------------------------------------------------------
__global__ void f2h_k(const float4* __restrict__ s, __half2* __restrict__ d, int n4)
{
    int i = blockIdx.x * blockDim.x + threadIdx.x;
    if (i < n4) {
        float4 v = s[i];
        d[2 * i]     = __floats2half2_rn(v.x, v.y);
        d[2 * i + 1] = __floats2half2_rn(v.z, v.w);
    }
}

// ---------------------------------------------------------------------------
// Window attention: one CTA per (window, head), 128 threads (4 warps).
// fp16 I/O, tf32 mma compute (known-good numerics).
// ---------------------------------------------------------------------------
__global__ __launch_bounds__(128) void win_attn(
    const __half* __restrict__ qkv, const float* __restrict__ bias,
    __half* __restrict__ outp)
{
    __shared__ float Qs[64][36];
    __shared__ float Ks[64][36];
    __shared__ float Vs[64][36];
    __shared__ float Ss[64][68];

    const int w   = blockIdx.x;
    const int h   = blockIdx.y;
    const int b   = w >> 10;
    const int rem = w & 1023;
    const int wh  = rem >> 5;
    const int ww  = rem & 31;
    const int base_l = (b << 16) + (wh << 3) * 256 + (ww << 3);

    const int tid = threadIdx.x;
    const float scale = 0.17677669529663687f;   // 1/sqrt(32)

    // load q,k,v tiles (64 x 32 halves each): 2 iters x 16B per tensor
#pragma unroll
    for (int it = 0; it < 2; it++) {
        int v   = tid + it * 128;               // 0..255
        int row = v >> 2;                       // token 0..63
        int c8  = (v & 3) << 3;                 // 0,8,16,24
        int l   = base_l + ((row >> 3) << 8) + (row & 7);
        const __half* rp = qkv + (size_t)l * 768 + (h << 5) + c8;
        uint4 qd = *(const uint4*)(rp);
        uint4 kd = *(const uint4*)(rp + 256);
        uint4 vd = *(const uint4*)(rp + 512);
        const __half2* qh = (const __half2*)&qd;
        const __half2* kh = (const __half2*)&kd;
        const __half2* vh = (const __half2*)&vd;
#pragma unroll
        for (int j = 0; j < 4; j++) {
            float2 qf = __half22float2(qh[j]);
            float2 kf = __half22float2(kh[j]);
            float2 vf = __half22float2(vh[j]);
            Qs[row][c8 + 2 * j]     = tf32r(qf.x * scale);
            Qs[row][c8 + 2 * j + 1] = tf32r(qf.y * scale);
            Ks[row][c8 + 2 * j]     = kf.x;   // fp16 values are tf32-exact
            Ks[row][c8 + 2 * j + 1] = kf.y;
            Vs[row][c8 + 2 * j]     = vf.x;
            Vs[row][c8 + 2 * j + 1] = vf.y;
        }
    }
    __syncthreads();

    const int lane = tid & 31, warp = tid >> 5;
    const int gid = lane >> 2, tig = lane & 3;
    const int mB = warp << 4;
    const int r0 = mB + gid, r1 = r0 + 8;

    // S = q*scale @ k^T  (64x64, each warp 16 rows)
    float c[8][4];
#pragma unroll
    for (int nf = 0; nf < 8; nf++)
#pragma unroll
        for (int r = 0; r < 4; r++) c[nf][r] = 0.f;

#pragma unroll
    for (int kc = 0; kc < 4; kc++) {
        uint32_t a[4];
        a[0] = __float_as_uint(Qs[r0][kc * 8 + tig]);
        a[1] = __float_as_uint(Qs[r1][kc * 8 + tig]);
        a[2] = __float_as_uint(Qs[r0][kc * 8 + tig + 4]);
        a[3] = __float_as_uint(Qs[r1][kc * 8 + tig + 4]);
#pragma unroll
        for (int nf = 0; nf < 8; nf++) {
            uint32_t bf[2];
            bf[0] = __float_as_uint(Ks[nf * 8 + gid][kc * 8 + tig]);
            bf[1] = __float_as_uint(Ks[nf * 8 + gid][kc * 8 + tig + 4]);
            mma8(c[nf], a, bf);
        }
    }

    // + bias, then row softmax
    const float* bp = bias + (h << 12);
    float mx0 = -1e30f, mx1 = -1e30f;
#pragma unroll
    for (int nf = 0; nf < 8; nf++) {
        int col = nf * 8 + 2 * tig;
        float2 b0 = *(const float2*)(bp + r0 * 64 + col);
        float2 b1 = *(const float2*)(bp + r1 * 64 + col);
        c[nf][0] += b0.x; c[nf][1] += b0.y;
        c[nf][2] += b1.x; c[nf][3] += b1.y;
        mx0 = fmaxf(mx0, fmaxf(c[nf][0], c[nf][1]));
        mx1 = fmaxf(mx1, fmaxf(c[nf][2], c[nf][3]));
    }
    mx0 = fmaxf(mx0, __shfl_xor_sync(0xffffffffu, mx0, 1));
    mx0 = fmaxf(mx0, __shfl_xor_sync(0xffffffffu, mx0, 2));
    mx1 = fmaxf(mx1, __shfl_xor_sync(0xffffffffu, mx1, 1));
    mx1 = fmaxf(mx1, __shfl_xor_sync(0xffffffffu, mx1, 2));

    float s0 = 0.f, s1 = 0.f;
#pragma unroll
    for (int nf = 0; nf < 8; nf++) {
        c[nf][0] = __expf(c[nf][0] - mx0); s0 += c[nf][0];
        c[nf][1] = __expf(c[nf][1] - mx0); s0 += c[nf][1];
        c[nf][2] = __expf(c[nf][2] - mx1); s1 += c[nf][2];
        c[nf][3] = __expf(c[nf][3] - mx1); s1 += c[nf][3];
    }
    s0 += __shfl_xor_sync(0xffffffffu, s0, 1);
    s0 += __shfl_xor_sync(0xffffffffu, s0, 2);
    s1 += __shfl_xor_sync(0xffffffffu, s1, 1);
    s1 += __shfl_xor_sync(0xffffffffu, s1, 2);
    float i0 = 1.f / s0, i1 = 1.f / s1;

#pragma unroll
    for (int nf = 0; nf < 8; nf++) {
        int col = nf * 8 + 2 * tig;
        Ss[r0][col]     = tf32r(c[nf][0] * i0);
        Ss[r0][col + 1] = tf32r(c[nf][1] * i0);
        Ss[r1][col]     = tf32r(c[nf][2] * i1);
        Ss[r1][col + 1] = tf32r(c[nf][3] * i1);
    }
    __syncthreads();

    // O = P @ V  (64x32)
    float o[4][4];
#pragma unroll
    for (int nf = 0; nf < 4; nf++)
#pragma unroll
        for (int r = 0; r < 4; r++) o[nf][r] = 0.f;

#pragma unroll
    for (int kc = 0; kc < 8; kc++) {
        uint32_t a[4];
        a[0] = __float_as_uint(Ss[r0][kc * 8 + tig]);
        a[1] = __float_as_uint(Ss[r1][kc * 8 + tig]);
        a[2] = __float_as_uint(Ss[r0][kc * 8 + tig + 4]);
        a[3] = __float_as_uint(Ss[r1][kc * 8 + tig + 4]);
#pragma unroll
        for (int nf = 0; nf < 4; nf++) {
            uint32_t bf[2];
            bf[0] = __float_as_uint(Vs[kc * 8 + tig    ][nf * 8 + gid]);
            bf[1] = __float_as_uint(Vs[kc * 8 + tig + 4][nf * 8 + gid]);
            mma8(o[nf], a, bf);
        }
    }

    // scatter fp16 to natural token order (GEMM3's A operand)
    const int l0 = base_l + ((r0 >> 3) << 8) + (r0 & 7);
    const int l1 = base_l + ((r1 >> 3) << 8) + (r1 & 7);
#pragma unroll
    for (int nf = 0; nf < 4; nf++) {
        int col = (h << 5) + nf * 8 + 2 * tig;
        *(__half2*)(outp + (size_t)l0 * 256 + col) = __floats2half2_rn(o[nf][0], o[nf][1]);
        *(__half2*)(outp + (size_t)l1 * 256 + col) = __floats2half2_rn(o[nf][2], o[nf][3]);
    }
}

// ---------------------------------------------------------------------------
// launch
// ---------------------------------------------------------------------------
extern "C" void kernel_launch(void* const* d_in, const int* in_sizes, int n_in,
                              void* d_out, int out_size)
{
    const float* x      = (const float*)d_in[0];
    const float* qkv_w  = (const float*)d_in[1];
    const float* proj_w = (const float*)d_in[2];
    const float* proj_b = (const float*)d_in[3];
    const float* bias   = (const float*)d_in[4];
    float* out = (float*)d_out;

    __half *x16, *wq16, *wp16, *qkv16, *att16;
    cudaGetSymbolAddress((void**)&x16,   g_x16);
    cudaGetSymbolAddress((void**)&wq16,  g_wq16);
    cudaGetSymbolAddress((void**)&wp16,  g_wp16);
    cudaGetSymbolAddress((void**)&qkv16, g_qkv);
    cudaGetSymbolAddress((void**)&att16, g_att);

    // fp32 -> fp16 pre-pass for all GEMM operands
    f2h_k<<<(Mtot * 256 / 4 + 255) / 256, 256>>>((const float4*)x,
                                                 (__half2*)x16, Mtot * 256 / 4);
    f2h_k<<<(768 * 256 / 4 + 255) / 256, 256>>>((const float4*)qkv_w,
                                                (__half2*)wq16, 768 * 256 / 4);
    f2h_k<<<(256 * 256 / 4 + 255) / 256, 256>>>((const float4*)proj_w,
                                                (__half2*)wp16, 256 * 256 / 4);

    // QKV projection: [262144,256] @ [768,256]^T -> fp16 [262144,768]
    gemm_f16<__half><<<dim3(768 / BN, Mtot / BM), 128>>>(x16, wq16, nullptr,
                                                         qkv16, 768, 256);
    // window attention (fp16 I/O, tf32 compute)
    win_attn<<<dim3(NWIN, NH_), 128>>>(qkv16, bias, att16);
    // output projection: [262144,256] @ [256,256]^T + b -> fp32 d_out
    gemm_f16<float><<<dim3(256 / BN, Mtot / BM), 128>>>(att16, wp16, proj_b,
                                                        out, 256, 256);
}

// round 12
// speedup vs baseline: 3.7497x; 1.2532x over previous
#include <cuda_runtime.h>
#include <cuda_fp16.h>
#include <cstdint>
#include <cstddef>

// Problem constants
#define B_    4
#define C_    256
#define NH_   8
#define Mtot  262144          // B * H * W tokens
#define NWIN  4096            // B * 32 * 32 windows

// Scratch (allocation-free rule: __device__ globals)
__device__ __half g_x16 [(size_t)Mtot * 256];   // x in fp16
__device__ __half g_wq16[768 * 256];            // qkv_w in fp16
__device__ __half g_wp16[256 * 256];            // proj_w in fp16
// qkv window-gathered: [3][4096 win][8 head][64 tok][32 dim] fp16
__device__ __half g_qkv [(size_t)3 * NWIN * NH_ * 64 * 32];
__device__ __half g_att [(size_t)Mtot * 256];   // attn out, natural order, fp16

// ---------------------------------------------------------------------------
// helpers
// ---------------------------------------------------------------------------
__device__ __forceinline__ void mma16(float c[4], const uint32_t a[4], const uint32_t b[2]) {
    asm volatile(
        "mma.sync.aligned.m16n8k16.row.col.f32.f16.f16.f32 "
        "{%0,%1,%2,%3}, {%4,%5,%6,%7}, {%8,%9}, {%0,%1,%2,%3};\n"
        : "+f"(c[0]), "+f"(c[1]), "+f"(c[2]), "+f"(c[3])
        : "r"(a[0]), "r"(a[1]), "r"(a[2]), "r"(a[3]), "r"(b[0]), "r"(b[1]));
}

__device__ __forceinline__ void cpa16(void* dst, const void* src) {
    uint32_t d = (uint32_t)__cvta_generic_to_shared(dst);
    asm volatile("cp.async.cg.shared.global [%0], [%1], 16;\n" :: "r"(d), "l"(src));
}
__device__ __forceinline__ void cpa_commit() {
    asm volatile("cp.async.commit_group;\n" ::: "memory");
}
template <int N>
__device__ __forceinline__ void cpa_wait() {
    asm volatile("cp.async.wait_group %0;\n" :: "n"(N) : "memory");
}

__device__ __forceinline__ uint32_t ld_h2(const __half* p) {
    return *(const uint32_t*)p;
}
__device__ __forceinline__ uint32_t pk_h2(float a, float b) {
    __half2 h = __floats2half2_rn(a, b);
    return *(uint32_t*)&h;
}

// ---------------------------------------------------------------------------
// fp16 GEMM, 2-stage cp.async pipeline (register-lean skeleton):
// C[M,N] = A[M,K] @ B[N,K]^T (+ bias[N]),  A,B fp16, accum fp32
// MODE 0: natural row-major OutT output.
// MODE 1: fp16 output scattered to window-gathered qkv layout
//         [3][win][head][64][32] (row = natural token, col in [0,768)).
// BM=128, BN=128, BKH=32 halves, 128 threads, 4 warps (2x2), warp tile 64x64
// ---------------------------------------------------------------------------
#define BM 128
#define BN 128
#define BKH 32
#define KPADH 40   // 40 halves = 80 B row stride, conflict-free

template <typename OutT, int MODE>
__global__ __launch_bounds__(128, 3) void gemm_f16(
    const __half* __restrict__ A, const __half* __restrict__ Bw,
    const float* __restrict__ bias, OutT* __restrict__ C,
    int N, int K)
{
    __shared__ __align__(16) __half As[2][BM][KPADH];   // 10 KB
    __shared__ __align__(16) __half Bs[2][BN][KPADH];   // 10 KB

    const int tid  = threadIdx.x;
    const int mT   = blockIdx.y * BM;
    const int nT   = blockIdx.x * BN;
    const int lane = tid & 31;
    const int warp = tid >> 5;
    const int gid  = lane >> 2;
    const int tig  = lane & 3;
    const int wm   = (warp & 1) * 64;
    const int wn   = (warp >> 1) * 64;

    float c[4][8][4];
#pragma unroll
    for (int i = 0; i < 4; i++)
#pragma unroll
        for (int j = 0; j < 8; j++)
#pragma unroll
            for (int r = 0; r < 4; r++) c[i][j][r] = 0.f;

    const int rc = tid >> 2;             // base row 0..31
    const int cc = (tid & 3) << 3;       // half offset 0,8,16,24

    auto issue = [&](int s, int k0) {
        const __half* ab = A  + (size_t)(mT + rc) * K + k0 + cc;
        const __half* bb = Bw + (size_t)(nT + rc) * K + k0 + cc;
#pragma unroll
        for (int it = 0; it < 4; it++) {
            int row = rc + it * 32;
            cpa16(&As[s][row][cc], ab + (size_t)it * 32 * K);
            cpa16(&Bs[s][row][cc], bb + (size_t)it * 32 * K);
        }
        cpa_commit();
    };

    issue(0, 0);
    const int NT = K >> 5;

    for (int kt = 0; kt < NT; kt++) {
        if (kt + 1 < NT) {
            issue((kt + 1) & 1, (kt + 1) * BKH);
            cpa_wait<1>();
        } else {
            cpa_wait<0>();
        }
        __syncthreads();

        const int s = kt & 1;
#pragma unroll
        for (int kk = 0; kk < BKH; kk += 16) {
            uint32_t af[4][4], bf[8][2];
#pragma unroll
            for (int mf = 0; mf < 4; mf++) {
                int m = wm + mf * 16 + gid;
                af[mf][0] = ld_h2(&As[s][m    ][kk + 2 * tig]);
                af[mf][1] = ld_h2(&As[s][m + 8][kk + 2 * tig]);
                af[mf][2] = ld_h2(&As[s][m    ][kk + 2 * tig + 8]);
                af[mf][3] = ld_h2(&As[s][m + 8][kk + 2 * tig + 8]);
            }
#pragma unroll
            for (int nf = 0; nf < 8; nf++) {
                int n = wn + nf * 8 + gid;
                bf[nf][0] = ld_h2(&Bs[s][n][kk + 2 * tig]);
                bf[nf][1] = ld_h2(&Bs[s][n][kk + 2 * tig + 8]);
            }
#pragma unroll
            for (int mf = 0; mf < 4; mf++)
#pragma unroll
                for (int nf = 0; nf < 8; nf++)
                    mma16(c[mf][nf], af[mf], bf[nf]);
        }
        __syncthreads();
    }

    // epilogue: per-fragment direct stores (register-lean)
#pragma unroll
    for (int mf = 0; mf < 4; mf++) {
#pragma unroll
        for (int nf = 0; nf < 8; nf++) {
            int row = mT + wm + mf * 16 + gid;
            int col = nT + wn + nf * 8 + 2 * tig;
            if (MODE == 1) {
                // window-gathered qkv scatter
                int t = col >> 8, hh = (col >> 5) & 7, d = col & 31;
#pragma unroll
                for (int rr = 0; rr < 2; rr++) {
                    int l = row + rr * 8;
                    int b = l >> 16, y = (l >> 8) & 255, x = l & 255;
                    int win = (b << 10) + ((y >> 3) << 5) + (x >> 3);
                    int pos = ((y & 7) << 3) + (x & 7);
                    size_t dst = ((((size_t)t * NWIN + win) * NH_ + hh) * 64 + pos) * 32 + d;
                    *(uint32_t*)((__half*)C + dst) =
                        pk_h2(c[mf][nf][2 * rr], c[mf][nf][2 * rr + 1]);
                }
            } else {
                float b0 = 0.f, b1 = 0.f;
                if (bias) { b0 = bias[col]; b1 = bias[col + 1]; }
                if (sizeof(OutT) == 2) {
                    *(uint32_t*)((__half*)C + (size_t)row * N + col) =
                        pk_h2(c[mf][nf][0] + b0, c[mf][nf][1] + b1);
                    *(uint32_t*)((__half*)C + (size_t)(row + 8) * N + col) =
                        pk_h2(c[mf][nf][2] + b0, c[mf][nf][3] + b1);
                } else {
                    *(float2*)((float*)C + (size_t)row * N + col) =
                        make_float2(c[mf][nf][0] + b0, c[mf][nf][1] + b1);
                    *(float2*)((float*)C + (size_t)(row + 8) * N + col) =
                        make_float2(c[mf][nf][2] + b0, c[mf][nf][3] + b1);
                }
            }
        }
    }
}

// ---------------------------------------------------------------------------
// fp32 -> fp16 conversion pre-pass
// ---------------------------------------------------------------------------
__global__ void f2h_k(const float4* __restrict__ s, __half2* __restrict__ d, int n4)
{
    int i = blockIdx.x * blockDim.x + threadIdx.x;
    if (i < n4) {
        float4 v = s[i];
        d[2 * i]     = __floats2half2_rn(v.x, v.y);
        d[2 * i + 1] = __floats2half2_rn(v.z, v.w);
    }
}

// ---------------------------------------------------------------------------
// Window attention v2: CTA = (window, head), 128 threads (4 warps).
// Contiguous 4KB q/k/v blocks, fp16 m16n8k16 MMAs, P kept in registers,
// scale + softmax normalization in fp32 after the MMAs.
// ---------------------------------------------------------------------------
__global__ __launch_bounds__(128) void win_attn(
    const __half* __restrict__ qkv, const float* __restrict__ bias,
    __half* __restrict__ outp)
{
    __shared__ __align__(16) __half Qs[64][KPADH];   // 5 KB
    __shared__ __align__(16) __half Ks[64][KPADH];   // 5 KB
    __shared__ __align__(16) __half Vt[32][72];      // 4.5 KB, dim-major V^T

    const int w = blockIdx.x;
    const int h = blockIdx.y;
    const size_t blk = ((size_t)w * NH_ + h) * 2048;   // 64*32
    const __half* qp = qkv + blk;
    const __half* kp = qkv + (size_t)NWIN * NH_ * 2048 + blk;
    const __half* vp = qkv + (size_t)2 * NWIN * NH_ * 2048 + blk;

    const int tid = threadIdx.x;
    const float scale = 0.17677669529663687f;   // 1/sqrt(32)

    // coalesced 16B loads; V transposed into Vt
#pragma unroll
    for (int it = 0; it < 2; it++) {
        int u   = tid + it * 128;               // 0..255
        int row = u >> 2;                       // token 0..63
        int c8  = (u & 3) << 3;                 // dim 0,8,16,24
        *(uint4*)&Qs[row][c8] = *(const uint4*)(qp + row * 32 + c8);
        *(uint4*)&Ks[row][c8] = *(const uint4*)(kp + row * 32 + c8);
        uint4 vv = *(const uint4*)(vp + row * 32 + c8);
        const __half* vh = (const __half*)&vv;
#pragma unroll
        for (int j = 0; j < 8; j++)
            Vt[c8 + j][row] = vh[j];
    }
    __syncthreads();

    const int lane = tid & 31, warp = tid >> 5;
    const int gid = lane >> 2, tig = lane & 3;
    const int mB = warp << 4;
    const int r0 = mB + gid, r1 = r0 + 8;

    // S = q @ k^T  (warp: 16 x 64), fp16 MMA, fp32 accum
    float c[8][4];
#pragma unroll
    for (int nf = 0; nf < 8; nf++)
#pragma unroll
        for (int r = 0; r < 4; r++) c[nf][r] = 0.f;

#pragma unroll
    for (int kc = 0; kc < 2; kc++) {
        uint32_t a[4];
        a[0] = ld_h2(&Qs[r0][16 * kc + 2 * tig]);
        a[1] = ld_h2(&Qs[r1][16 * kc + 2 * tig]);
        a[2] = ld_h2(&Qs[r0][16 * kc + 2 * tig + 8]);
        a[3] = ld_h2(&Qs[r1][16 * kc + 2 * tig + 8]);
#pragma unroll
        for (int nf = 0; nf < 8; nf++) {
            uint32_t bf[2];
            bf[0] = ld_h2(&Ks[nf * 8 + gid][16 * kc + 2 * tig]);
            bf[1] = ld_h2(&Ks[nf * 8 + gid][16 * kc + 2 * tig + 8]);
            mma16(c[nf], a, bf);
        }
    }

    // scale (fp32) + bias, then row softmax
    const float* bp = bias + (h << 12);
    float mx0 = -1e30f, mx1 = -1e30f;
#pragma unroll
    for (int nf = 0; nf < 8; nf++) {
        int col = nf * 8 + 2 * tig;
        float2 b0 = *(const float2*)(bp + r0 * 64 + col);
        float2 b1 = *(const float2*)(bp + r1 * 64 + col);
        c[nf][0] = c[nf][0] * scale + b0.x;
        c[nf][1] = c[nf][1] * scale + b0.y;
        c[nf][2] = c[nf][2] * scale + b1.x;
        c[nf][3] = c[nf][3] * scale + b1.y;
        mx0 = fmaxf(mx0, fmaxf(c[nf][0], c[nf][1]));
        mx1 = fmaxf(mx1, fmaxf(c[nf][2], c[nf][3]));
    }
    mx0 = fmaxf(mx0, __shfl_xor_sync(0xffffffffu, mx0, 1));
    mx0 = fmaxf(mx0, __shfl_xor_sync(0xffffffffu, mx0, 2));
    mx1 = fmaxf(mx1, __shfl_xor_sync(0xffffffffu, mx1, 1));
    mx1 = fmaxf(mx1, __shfl_xor_sync(0xffffffffu, mx1, 2));

    float s0 = 0.f, s1 = 0.f;
#pragma unroll
    for (int nf = 0; nf < 8; nf++) {
        c[nf][0] = __expf(c[nf][0] - mx0); s0 += c[nf][0];
        c[nf][1] = __expf(c[nf][1] - mx0); s0 += c[nf][1];
        c[nf][2] = __expf(c[nf][2] - mx1); s1 += c[nf][2];
        c[nf][3] = __expf(c[nf][3] - mx1); s1 += c[nf][3];
    }
    s0 += __shfl_xor_sync(0xffffffffu, s0, 1);
    s0 += __shfl_xor_sync(0xffffffffu, s0, 2);
    s1 += __shfl_xor_sync(0xffffffffu, s1, 1);
    s1 += __shfl_xor_sync(0xffffffffu, s1, 2);
    const float i0 = 1.f / s0, i1 = 1.f / s1;

    // O = P @ V: P re-packed from S accumulators directly into A-fragments
    float o[4][4];
#pragma unroll
    for (int nf = 0; nf < 4; nf++)
#pragma unroll
        for (int r = 0; r < 4; r++) o[nf][r] = 0.f;

#pragma unroll
    for (int kc = 0; kc < 4; kc++) {
        uint32_t a[4];
        a[0] = pk_h2(c[2 * kc][0],     c[2 * kc][1]);
        a[1] = pk_h2(c[2 * kc][2],     c[2 * kc][3]);
        a[2] = pk_h2(c[2 * kc + 1][0], c[2 * kc + 1][1]);
        a[3] = pk_h2(c[2 * kc + 1][2], c[2 * kc + 1][3]);
#pragma unroll
        for (int nf = 0; nf < 4; nf++) {
            uint32_t bf[2];
            bf[0] = ld_h2(&Vt[nf * 8 + gid][16 * kc + 2 * tig]);
            bf[1] = ld_h2(&Vt[nf * 8 + gid][16 * kc + 2 * tig + 8]);
            mma16(o[nf], a, bf);
        }
    }

    // normalize rows (deferred softmax denom) and scatter fp16, natural order
    const int b   = w >> 10;
    const int wh  = (w >> 5) & 31;
    const int ww  = w & 31;
    const int base_l = (b << 16) + (wh << 3) * 256 + (ww << 3);
    const int l0 = base_l + ((r0 >> 3) << 8) + (r0 & 7);
    const int l1 = base_l + ((r1 >> 3) << 8) + (r1 & 7);
#pragma unroll
    for (int nf = 0; nf < 4; nf++) {
        int col = (h << 5) + nf * 8 + 2 * tig;
        *(uint32_t*)(outp + (size_t)l0 * 256 + col) =
            pk_h2(o[nf][0] * i0, o[nf][1] * i0);
        *(uint32_t*)(outp + (size_t)l1 * 256 + col) =
            pk_h2(o[nf][2] * i1, o[nf][3] * i1);
    }
}

// ---------------------------------------------------------------------------
// launch
// ---------------------------------------------------------------------------
extern "C" void kernel_launch(void* const* d_in, const int* in_sizes, int n_in,
                              void* d_out, int out_size)
{
    const float* x      = (const float*)d_in[0];
    const float* qkv_w  = (const float*)d_in[1];
    const float* proj_w = (const float*)d_in[2];
    const float* proj_b = (const float*)d_in[3];
    const float* bias   = (const float*)d_in[4];
    float* out = (float*)d_out;

    __half *x16, *wq16, *wp16, *qkv16, *att16;
    cudaGetSymbolAddress((void**)&x16,   g_x16);
    cudaGetSymbolAddress((void**)&wq16,  g_wq16);
    cudaGetSymbolAddress((void**)&wp16,  g_wp16);
    cudaGetSymbolAddress((void**)&qkv16, g_qkv);
    cudaGetSymbolAddress((void**)&att16, g_att);

    // fp32 -> fp16 pre-pass for all GEMM operands
    f2h_k<<<(Mtot * 256 / 4 + 255) / 256, 256>>>((const float4*)x,
                                                 (__half2*)x16, Mtot * 256 / 4);
    f2h_k<<<(768 * 256 / 4 + 255) / 256, 256>>>((const float4*)qkv_w,
                                                (__half2*)wq16, 768 * 256 / 4);
    f2h_k<<<(256 * 256 / 4 + 255) / 256, 256>>>((const float4*)proj_w,
                                                (__half2*)wp16, 256 * 256 / 4);

    // QKV projection -> window-gathered fp16 qkv layout
    gemm_f16<__half, 1><<<dim3(768 / BN, Mtot / BM), 128>>>(x16, wq16, nullptr,
                                                            qkv16, 768, 256);
    // window attention (fp16 MMA, register-resident P)
    win_attn<<<dim3(NWIN, NH_), 128>>>(qkv16, bias, att16);
    // output projection: [262144,256] @ [256,256]^T + b -> fp32 d_out
    gemm_f16<float, 0><<<dim3(256 / BN, Mtot / BM), 128>>>(att16, wp16, proj_b,
                                                           out, 256, 256);
}

// round 13
// speedup vs baseline: 3.9888x; 1.0638x over previous
#include <cuda_runtime.h>
#include <cuda_fp16.h>
#include <cstdint>
#include <cstddef>

// Problem constants
#define B_    4
#define C_    256
#define NH_   8
#define Mtot  262144          // B * H * W tokens
#define NWIN  4096            // B * 32 * 32 windows

// Scratch (allocation-free rule: __device__ globals)
__device__ __half g_x16 [(size_t)Mtot * 256];   // x in fp16
__device__ __half g_wq16[768 * 256];            // qkv_w in fp16
__device__ __half g_wp16[256 * 256];            // proj_w in fp16
// qkv window-gathered: [3][4096 win][8 head][64 tok][32 dim] fp16
__device__ __half g_qkv [(size_t)3 * NWIN * NH_ * 64 * 32];
__device__ __half g_att [(size_t)Mtot * 256];   // attn out, natural order, fp16

// ---------------------------------------------------------------------------
// helpers
// ---------------------------------------------------------------------------
__device__ __forceinline__ void mma16(float c[4], const uint32_t a[4], const uint32_t b[2]) {
    asm volatile(
        "mma.sync.aligned.m16n8k16.row.col.f32.f16.f16.f32 "
        "{%0,%1,%2,%3}, {%4,%5,%6,%7}, {%8,%9}, {%0,%1,%2,%3};\n"
        : "+f"(c[0]), "+f"(c[1]), "+f"(c[2]), "+f"(c[3])
        : "r"(a[0]), "r"(a[1]), "r"(a[2]), "r"(a[3]), "r"(b[0]), "r"(b[1]));
}

__device__ __forceinline__ void ldsm4(uint32_t& r0, uint32_t& r1, uint32_t& r2,
                                      uint32_t& r3, uint32_t addr) {
    asm volatile("ldmatrix.sync.aligned.m8n8.x4.shared.b16 {%0,%1,%2,%3}, [%4];\n"
                 : "=r"(r0), "=r"(r1), "=r"(r2), "=r"(r3) : "r"(addr));
}

__device__ __forceinline__ void cpa16(void* dst, const void* src) {
    uint32_t d = (uint32_t)__cvta_generic_to_shared(dst);
    asm volatile("cp.async.cg.shared.global [%0], [%1], 16;\n" :: "r"(d), "l"(src));
}
__device__ __forceinline__ void cpa_commit() {
    asm volatile("cp.async.commit_group;\n" ::: "memory");
}
template <int N>
__device__ __forceinline__ void cpa_wait() {
    asm volatile("cp.async.wait_group %0;\n" :: "n"(N) : "memory");
}

__device__ __forceinline__ uint32_t ld_h2(const __half* p) {
    return *(const uint32_t*)p;
}
__device__ __forceinline__ uint32_t pk_h2(float a, float b) {
    __half2 h = __floats2half2_rn(a, b);
    return *(uint32_t*)&h;
}

// ---------------------------------------------------------------------------
// fp16 GEMM, 2-stage cp.async pipeline + ldmatrix fragment loads:
// C[M,N] = A[M,K] @ B[N,K]^T (+ bias[N]),  A,B fp16, accum fp32
// MODE 0: natural row-major OutT output.
// MODE 1: fp16 output scattered to window-gathered qkv layout
//         [3][win][head][64][32] (row = natural token, col in [0,768)).
// BM=128, BN=128, BKH=32 halves, 128 threads, 4 warps (2x2), warp tile 64x64
// smem [2][128][40] halves: 80B row stride, LDSM-phase conflict-free
// ---------------------------------------------------------------------------
#define BM 128
#define BN 128
#define BKH 32
#define KPADH 40                       // 40 halves = 80 B row stride
#define STAGEB (BM * KPADH * 2)        // 10240 B per stage

template <typename OutT, int MODE>
__global__ __launch_bounds__(128, 3) void gemm_f16(
    const __half* __restrict__ A, const __half* __restrict__ Bw,
    const float* __restrict__ bias, OutT* __restrict__ C,
    int N, int K)
{
    __shared__ __align__(16) __half As[2][BM][KPADH];   // 20 KB
    __shared__ __align__(16) __half Bs[2][BM][KPADH];   // 20 KB

    const int tid  = threadIdx.x;
    const int mT   = blockIdx.y * BM;
    const int nT   = blockIdx.x * BN;
    const int lane = tid & 31;
    const int warp = tid >> 5;
    const int gid  = lane >> 2;
    const int tig  = lane & 3;
    const int wm   = (warp & 1) * 64;
    const int wn   = (warp >> 1) * 64;

    float c[4][8][4];
#pragma unroll
    for (int i = 0; i < 4; i++)
#pragma unroll
        for (int j = 0; j < 8; j++)
#pragma unroll
            for (int r = 0; r < 4; r++) c[i][j][r] = 0.f;

    const int rc = tid >> 2;             // base row 0..31
    const int cc = (tid & 3) << 3;       // half offset 0,8,16,24

    auto issue = [&](int s, int k0) {
        const __half* ab = A  + (size_t)(mT + rc) * K + k0 + cc;
        const __half* bb = Bw + (size_t)(nT + rc) * K + k0 + cc;
#pragma unroll
        for (int it = 0; it < 4; it++) {
            int row = rc + it * 32;
            cpa16(&As[s][row][cc], ab + (size_t)it * 32 * K);
            cpa16(&Bs[s][row][cc], bb + (size_t)it * 32 * K);
        }
        cpa_commit();
    };

    issue(0, 0);
    const int NT = K >> 5;

    // ldmatrix per-lane offsets (bytes within a stage tile)
    // A x4 quadrants: {(m,k0),(m+8,k0),(m,k8),(m+8,k8)}
    const uint32_t aoff = ((lane & 7) + ((lane >> 3) & 1) * 8) * 80 +
                          ((lane >> 4) & 1) * 16;
    // B x4 quadrants: {(n,k0),(n,k8),(n+8,k0),(n+8,k8)}
    const uint32_t boff = ((lane & 7) + ((lane >> 4) & 1) * 8) * 80 +
                          ((lane >> 3) & 1) * 16;
    const uint32_t aBase = (uint32_t)__cvta_generic_to_shared(&As[0][0][0]) +
                           (uint32_t)(wm * 80) + aoff;
    const uint32_t bBase = (uint32_t)__cvta_generic_to_shared(&Bs[0][0][0]) +
                           (uint32_t)(wn * 80) + boff;

    for (int kt = 0; kt < NT; kt++) {
        if (kt + 1 < NT) {
            issue((kt + 1) & 1, (kt + 1) * BKH);
            cpa_wait<1>();
        } else {
            cpa_wait<0>();
        }
        __syncthreads();

        const int s = kt & 1;
        const uint32_t aS = aBase + s * STAGEB;
        const uint32_t bS = bBase + s * STAGEB;
#pragma unroll
        for (int kk = 0; kk < BKH; kk += 16) {
            uint32_t af[4][4], bf[8][2];
#pragma unroll
            for (int mf = 0; mf < 4; mf++)
                ldsm4(af[mf][0], af[mf][1], af[mf][2], af[mf][3],
                      aS + mf * (16 * 80) + kk * 2);
#pragma unroll
            for (int np = 0; np < 4; np++)
                ldsm4(bf[2 * np][0], bf[2 * np][1], bf[2 * np + 1][0],
                      bf[2 * np + 1][1], bS + np * (16 * 80) + kk * 2);
#pragma unroll
            for (int mf = 0; mf < 4; mf++)
#pragma unroll
                for (int nf = 0; nf < 8; nf++)
                    mma16(c[mf][nf], af[mf], bf[nf]);
        }
        __syncthreads();
    }

    // epilogue: per-fragment direct stores (register-lean)
#pragma unroll
    for (int mf = 0; mf < 4; mf++) {
#pragma unroll
        for (int nf = 0; nf < 8; nf++) {
            int row = mT + wm + mf * 16 + gid;
            int col = nT + wn + nf * 8 + 2 * tig;
            if (MODE == 1) {
                // window-gathered qkv scatter
                int t = col >> 8, hh = (col >> 5) & 7, d = col & 31;
#pragma unroll
                for (int rr = 0; rr < 2; rr++) {
                    int l = row + rr * 8;
                    int b = l >> 16, y = (l >> 8) & 255, x = l & 255;
                    int win = (b << 10) + ((y >> 3) << 5) + (x >> 3);
                    int pos = ((y & 7) << 3) + (x & 7);
                    size_t dst = ((((size_t)t * NWIN + win) * NH_ + hh) * 64 + pos) * 32 + d;
                    *(uint32_t*)((__half*)C + dst) =
                        pk_h2(c[mf][nf][2 * rr], c[mf][nf][2 * rr + 1]);
                }
            } else {
                float b0 = 0.f, b1 = 0.f;
                if (bias) { b0 = bias[col]; b1 = bias[col + 1]; }
                if (sizeof(OutT) == 2) {
                    *(uint32_t*)((__half*)C + (size_t)row * N + col) =
                        pk_h2(c[mf][nf][0] + b0, c[mf][nf][1] + b1);
                    *(uint32_t*)((__half*)C + (size_t)(row + 8) * N + col) =
                        pk_h2(c[mf][nf][2] + b0, c[mf][nf][3] + b1);
                } else {
                    *(float2*)((float*)C + (size_t)row * N + col) =
                        make_float2(c[mf][nf][0] + b0, c[mf][nf][1] + b1);
                    *(float2*)((float*)C + (size_t)(row + 8) * N + col) =
                        make_float2(c[mf][nf][2] + b0, c[mf][nf][3] + b1);
                }
            }
        }
    }
}

// ---------------------------------------------------------------------------
// fp32 -> fp16 conversion pre-pass
// ---------------------------------------------------------------------------
__global__ void f2h_k(const float4* __restrict__ s, __half2* __restrict__ d, int n4)
{
    int i = blockIdx.x * blockDim.x + threadIdx.x;
    if (i < n4) {
        float4 v = s[i];
        d[2 * i]     = __floats2half2_rn(v.x, v.y);
        d[2 * i + 1] = __floats2half2_rn(v.z, v.w);
    }
}

// ---------------------------------------------------------------------------
// Window attention v2: CTA = (window, head), 128 threads (4 warps).
// Contiguous 4KB q/k/v blocks, fp16 m16n8k16 MMAs, P kept in registers,
// scale + softmax normalization in fp32 after the MMAs.
// ---------------------------------------------------------------------------
__global__ __launch_bounds__(128) void win_attn(
    const __half* __restrict__ qkv, const float* __restrict__ bias,
    __half* __restrict__ outp)
{
    __shared__ __align__(16) __half Qs[64][KPADH];   // 5 KB
    __shared__ __align__(16) __half Ks[64][KPADH];   // 5 KB
    __shared__ __align__(16) __half Vt[32][72];      // 4.5 KB, dim-major V^T

    const int w = blockIdx.x;
    const int h = blockIdx.y;
    const size_t blk = ((size_t)w * NH_ + h) * 2048;   // 64*32
    const __half* qp = qkv + blk;
    const __half* kp = qkv + (size_t)NWIN * NH_ * 2048 + blk;
    const __half* vp = qkv + (size_t)2 * NWIN * NH_ * 2048 + blk;

    const int tid = threadIdx.x;
    const float scale = 0.17677669529663687f;   // 1/sqrt(32)

    // coalesced 16B loads; V transposed into Vt
#pragma unroll
    for (int it = 0; it < 2; it++) {
        int u   = tid + it * 128;               // 0..255
        int row = u >> 2;                       // token 0..63
        int c8  = (u & 3) << 3;                 // dim 0,8,16,24
        *(uint4*)&Qs[row][c8] = *(const uint4*)(qp + row * 32 + c8);
        *(uint4*)&Ks[row][c8] = *(const uint4*)(kp + row * 32 + c8);
        uint4 vv = *(const uint4*)(vp + row * 32 + c8);
        const __half* vh = (const __half*)&vv;
#pragma unroll
        for (int j = 0; j < 8; j++)
            Vt[c8 + j][row] = vh[j];
    }
    __syncthreads();

    const int lane = tid & 31, warp = tid >> 5;
    const int gid = lane >> 2, tig = lane & 3;
    const int mB = warp << 4;
    const int r0 = mB + gid, r1 = r0 + 8;

    // S = q @ k^T  (warp: 16 x 64), fp16 MMA, fp32 accum
    float c[8][4];
#pragma unroll
    for (int nf = 0; nf < 8; nf++)
#pragma unroll
        for (int r = 0; r < 4; r++) c[nf][r] = 0.f;

#pragma unroll
    for (int kc = 0; kc < 2; kc++) {
        uint32_t a[4];
        a[0] = ld_h2(&Qs[r0][16 * kc + 2 * tig]);
        a[1] = ld_h2(&Qs[r1][16 * kc + 2 * tig]);
        a[2] = ld_h2(&Qs[r0][16 * kc + 2 * tig + 8]);
        a[3] = ld_h2(&Qs[r1][16 * kc + 2 * tig + 8]);
#pragma unroll
        for (int nf = 0; nf < 8; nf++) {
            uint32_t bf[2];
            bf[0] = ld_h2(&Ks[nf * 8 + gid][16 * kc + 2 * tig]);
            bf[1] = ld_h2(&Ks[nf * 8 + gid][16 * kc + 2 * tig + 8]);
            mma16(c[nf], a, bf);
        }
    }

    // scale (fp32) + bias, then row softmax
    const float* bp = bias + (h << 12);
    float mx0 = -1e30f, mx1 = -1e30f;
#pragma unroll
    for (int nf = 0; nf < 8; nf++) {
        int col = nf * 8 + 2 * tig;
        float2 b0 = *(const float2*)(bp + r0 * 64 + col);
        float2 b1 = *(const float2*)(bp + r1 * 64 + col);
        c[nf][0] = c[nf][0] * scale + b0.x;
        c[nf][1] = c[nf][1] * scale + b0.y;
        c[nf][2] = c[nf][2] * scale + b1.x;
        c[nf][3] = c[nf][3] * scale + b1.y;
        mx0 = fmaxf(mx0, fmaxf(c[nf][0], c[nf][1]));
        mx1 = fmaxf(mx1, fmaxf(c[nf][2], c[nf][3]));
    }
    mx0 = fmaxf(mx0, __shfl_xor_sync(0xffffffffu, mx0, 1));
    mx0 = fmaxf(mx0, __shfl_xor_sync(0xffffffffu, mx0, 2));
    mx1 = fmaxf(mx1, __shfl_xor_sync(0xffffffffu, mx1, 1));
    mx1 = fmaxf(mx1, __shfl_xor_sync(0xffffffffu, mx1, 2));

    float s0 = 0.f, s1 = 0.f;
#pragma unroll
    for (int nf = 0; nf < 8; nf++) {
        c[nf][0] = __expf(c[nf][0] - mx0); s0 += c[nf][0];
        c[nf][1] = __expf(c[nf][1] - mx0); s0 += c[nf][1];
        c[nf][2] = __expf(c[nf][2] - mx1); s1 += c[nf][2];
        c[nf][3] = __expf(c[nf][3] - mx1); s1 += c[nf][3];
    }
    s0 += __shfl_xor_sync(0xffffffffu, s0, 1);
    s0 += __shfl_xor_sync(0xffffffffu, s0, 2);
    s1 += __shfl_xor_sync(0xffffffffu, s1, 1);
    s1 += __shfl_xor_sync(0xffffffffu, s1, 2);
    const float i0 = 1.f / s0, i1 = 1.f / s1;

    // O = P @ V: P re-packed from S accumulators directly into A-fragments
    float o[4][4];
#pragma unroll
    for (int nf = 0; nf < 4; nf++)
#pragma unroll
        for (int r = 0; r < 4; r++) o[nf][r] = 0.f;

#pragma unroll
    for (int kc = 0; kc < 4; kc++) {
        uint32_t a[4];
        a[0] = pk_h2(c[2 * kc][0],     c[2 * kc][1]);
        a[1] = pk_h2(c[2 * kc][2],     c[2 * kc][3]);
        a[2] = pk_h2(c[2 * kc + 1][0], c[2 * kc + 1][1]);
        a[3] = pk_h2(c[2 * kc + 1][2], c[2 * kc + 1][3]);
#pragma unroll
        for (int nf = 0; nf < 4; nf++) {
            uint32_t bf[2];
            bf[0] = ld_h2(&Vt[nf * 8 + gid][16 * kc + 2 * tig]);
            bf[1] = ld_h2(&Vt[nf * 8 + gid][16 * kc + 2 * tig + 8]);
            mma16(o[nf], a, bf);
        }
    }

    // normalize rows (deferred softmax denom) and scatter fp16, natural order
    const int b   = w >> 10;
    const int wh  = (w >> 5) & 31;
    const int ww  = w & 31;
    const int base_l = (b << 16) + (wh << 3) * 256 + (ww << 3);
    const int l0 = base_l + ((r0 >> 3) << 8) + (r0 & 7);
    const int l1 = base_l + ((r1 >> 3) << 8) + (r1 & 7);
#pragma unroll
    for (int nf = 0; nf < 4; nf++) {
        int col = (h << 5) + nf * 8 + 2 * tig;
        *(uint32_t*)(outp + (size_t)l0 * 256 + col) =
            pk_h2(o[nf][0] * i0, o[nf][1] * i0);
        *(uint32_t*)(outp + (size_t)l1 * 256 + col) =
            pk_h2(o[nf][2] * i1, o[nf][3] * i1);
    }
}

// ---------------------------------------------------------------------------
// launch
// ---------------------------------------------------------------------------
extern "C" void kernel_launch(void* const* d_in, const int* in_sizes, int n_in,
                              void* d_out, int out_size)
{
    const float* x      = (const float*)d_in[0];
    const float* qkv_w  = (const float*)d_in[1];
    const float* proj_w = (const float*)d_in[2];
    const float* proj_b = (const float*)d_in[3];
    const float* bias   = (const float*)d_in[4];
    float* out = (float*)d_out;

    __half *x16, *wq16, *wp16, *qkv16, *att16;
    cudaGetSymbolAddress((void**)&x16,   g_x16);
    cudaGetSymbolAddress((void**)&wq16,  g_wq16);
    cudaGetSymbolAddress((void**)&wp16,  g_wp16);
    cudaGetSymbolAddress((void**)&qkv16, g_qkv);
    cudaGetSymbolAddress((void**)&att16, g_att);

    // fp32 -> fp16 pre-pass for all GEMM operands
    f2h_k<<<(Mtot * 256 / 4 + 255) / 256, 256>>>((const float4*)x,
                                                 (__half2*)x16, Mtot * 256 / 4);
    f2h_k<<<(768 * 256 / 4 + 255) / 256, 256>>>((const float4*)qkv_w,
                                                (__half2*)wq16, 768 * 256 / 4);
    f2h_k<<<(256 * 256 / 4 + 255) / 256, 256>>>((const float4*)proj_w,
                                                (__half2*)wp16, 256 * 256 / 4);

    // QKV projection -> window-gathered fp16 qkv layout
    gemm_f16<__half, 1><<<dim3(768 / BN, Mtot / BM), 128>>>(x16, wq16, nullptr,
                                                            qkv16, 768, 256);
    // window attention (fp16 MMA, register-resident P)
    win_attn<<<dim3(NWIN, NH_), 128>>>(qkv16, bias, att16);
    // output projection: [262144,256] @ [256,256]^T + b -> fp32 d_out
    gemm_f16<float, 0><<<dim3(256 / BN, Mtot / BM), 128>>>(att16, wp16, proj_b,
                                                           out, 256, 256);
}